// round 15
// baseline (speedup 1.0000x reference)
#include <cuda_runtime.h>
#include <cstdint>

#define HH 128
#define WW 192
#define CC_TOT 256
#define C_HALF 128
#define BB 8
#define TILE_W 32
#define TILE_H 16
#define HALO_H 24
#define CHUNK 4
#define NCHUNK (C_HALF / CHUNK)           // 32 per half-CTA
#define NT 256
#define PLANE ((size_t)HH * WW)
#define NTILE 384

#define HROW 176
#define CROW 144
#define PSEC (HALO_H * HROW)              // 4224
#define CSEC (TILE_H * CROW)              // 2304
#define PREV_BUF (CHUNK * PSEC)           // 16896
#define CURR_BUF (CHUNK * CSEC)           // 9216
#define SM_PREV 0
#define SM_CURR (3 * PREV_BUF)            // 50688
#define SM_SSP  (SM_CURR + 3 * CURR_BUF)  // 78336
#define SM_CIV  (SM_SSP + PSEC)           // 82560
#define SM_FLAG (SM_CIV + CSEC)           // 84864
#define SMEM_BYTES (SM_FLAG + 16)         // 84880 -> 2 CTAs/SM

typedef unsigned long long u64;

// cross-CTA combine scratch (zero-initialized at module load; counters monotonic)
__device__ u64 g_acc[(size_t)NTILE * 34 * 256];
__device__ u64 g_aux[(size_t)NTILE * 4 * 256];
__device__ unsigned int g_cnt[NTILE];
__device__ unsigned int g_rdy[NTILE];

__device__ __forceinline__ void F2(u64 &d, u64 a, u64 b) {
    asm("fma.rn.f32x2 %0, %1, %2, %0;" : "+l"(d) : "l"(a), "l"(b));
}
__device__ __forceinline__ void ADD2(u64 &d, u64 a) {
    asm("add.rn.f32x2 %0, %0, %1;" : "+l"(d) : "l"(a));
}
__device__ __forceinline__ u64 M2(u64 a, u64 b) {
    u64 d; asm("mul.rn.f32x2 %0, %1, %2;" : "=l"(d) : "l"(a), "l"(b)); return d;
}
__device__ __forceinline__ u64 PK(unsigned a, unsigned b) {
    u64 d; asm("mov.b64 %0, {%1, %2};" : "=l"(d) : "r"(a), "r"(b)); return d;
}
__device__ __forceinline__ unsigned LOW(u64 a) {
    unsigned l, h; asm("mov.b64 {%0, %1}, %2;" : "=r"(l), "=r"(h) : "l"(a)); return l;
}
__device__ __forceinline__ unsigned HIW(u64 a) {
    unsigned l, h; asm("mov.b64 {%0, %1}, %2;" : "=r"(l), "=r"(h) : "l"(a)); return h;
}
__device__ __forceinline__ float FL(u64 a) { return __uint_as_float(LOW(a)); }
__device__ __forceinline__ float FH(u64 a) { return __uint_as_float(HIW(a)); }
__device__ __forceinline__ void cp16(uint32_t dst, const void* src, int szbytes) {
    asm volatile("cp.async.cg.shared.global [%0], [%1], 16, %2;\n"
                 :: "r"(dst), "l"(src), "r"(szbytes) : "memory");
}
__device__ __forceinline__ ulonglong2 LD2(const void* p) {
    return *reinterpret_cast<const ulonglong2*>(p);
}
__device__ __forceinline__ u64 LD1(const void* p) {
    return *reinterpret_cast<const u64*>(p);
}
__device__ __forceinline__ float GRD(float v) { return v > 0.f ? rsqrtf(v) : 0.f; }

__global__ void __launch_bounds__(NT, 2)
corr_kernel(const float* __restrict__ curr, const float* __restrict__ prev,
            float* __restrict__ out)
{
    extern __shared__ char smem[];

    const int tid = threadIdx.x;
    const int grp = tid >> 6;          // 4 groups of 64 threads
    const int gt  = tid & 63;
    const int xg  = gt & 3;            // 4 x-groups of 8 pixels
    const int ty  = gt >> 2;           // 16 rows
    const int x0  = blockIdx.x * TILE_W;
    const int y0  = blockIdx.y * TILE_H;
    const int tz  = blockIdx.z;
    const int half = tz & 1;
    const int bb  = tz >> 1;
    const int tileId = bb * 48 + blockIdx.y * 6 + blockIdx.x;

    const char* currB = (const char*)(curr + ((size_t)bb * CC_TOT + (size_t)half * C_HALF) * PLANE);
    const char* prevB = (const char*)(prev + ((size_t)bb * CC_TOT + (size_t)half * C_HALF) * PLANE);
    const uint32_t smA = (uint32_t)__cvta_generic_to_shared(smem);

    // ---- staging precompute ----
    const int psy = tid / 10, psx = tid - psy * 10;   // 240 prev f4 slots
    const int pgy = y0 - 4 + psy, pgx = x0 - 4 + psx * 4;
    const bool doP = (tid < 240);
    const bool pok = doP && ((unsigned)pgy < HH) && ((unsigned)pgx < WW);
    const int pOff = pok ? (pgy * WW + pgx) * 4 : 0;
    const int psz  = pok ? 16 : 0;
    const uint32_t pRel = (uint32_t)(psy * HROW + psx * 16);
    const bool doC = (tid >= 128);
    const int cslot = tid - 128;
    const int csy = cslot >> 3, csx = cslot & 7;
    const int cOff = ((y0 + csy) * WW + x0 + csx * 4) * 4;
    const uint32_t cRel = (uint32_t)(csy * CROW + csx * 16);

    // ---- boundary prev-sq: 112 slots on G1(56)/G3(56) ----
    int fbj = -1;
    if (grp == 1)      { if (gt < 56) fbj = gt; }
    else if (grp == 3) { if (gt < 56) fbj = 56 + gt; }
    const bool doFB = (fbj >= 0);
    int fbRow = 0, fbCol = 0;
    if (fbj >= 0) {
        if (fbj < 40)      { fbRow = fbj / 10; fbCol = fbj - fbRow * 10; }
        else if (fbj < 80) { int i = fbj - 40; fbRow = 20 + i / 10; fbCol = i - (i / 10) * 10; }
        else               { int i = fbj - 80; fbRow = 4 + (i >> 1); fbCol = (i & 1) ? 9 : 0; }
    }
    const uint32_t fbOff = (uint32_t)(fbRow * HROW + fbCol * 16);

    // ---- accumulators (layout as R12) ----
    u64 acc[34];
    #pragma unroll
    for (int i = 0; i < 34; i++) acc[i] = 0ull;
    u64 aux[4];
    #pragma unroll
    for (int i = 0; i < 4; i++) aux[i] = 0ull;

    auto issue = [&](const char* srcP, const char* srcC, uint32_t dP, uint32_t dC) {
        #pragma unroll
        for (int cc = 0; cc < CHUNK; cc++) {
            const size_t so = (size_t)cc * PLANE * 4;
            if (doP) cp16(dP + cc * PSEC + pRel, srcP + so + pOff, psz);
            if (doC) cp16(dC + cc * CSEC + cRel, srcC + so + cOff, 16);
        }
        asm volatile("cp.async.commit_group;\n" ::: "memory");
    };

    issue(prevB, currB, smA + SM_PREV, smA + SM_CURR);
    issue(prevB + (size_t)CHUNK * PLANE * 4, currB + (size_t)CHUNK * PLANE * 4,
          smA + SM_PREV + PREV_BUF, smA + SM_CURR + CURR_BUF);

    const char* srcPs = prevB + (size_t)2 * CHUNK * PLANE * 4;
    const char* srcCs = currB + (size_t)2 * CHUNK * PLANE * 4;
    int bC = 0, bS = 2;

    const int tyOff = ty * HROW + xg * 32;
    const int cvOff = ty * CROW + xg * 32;

#define FROW(O, RB) do { \
    const ulonglong2 q0 = LD2(RB), q1 = LD2((RB) + 16), q2 = LD2((RB) + 32), q3 = LD2((RB) + 48); \
    F2(acc[(O)*4+0],cv01,q0.x); F2(acc[(O)*4+1],cv23,q0.y); F2(acc[(O)*4+2],cv45,q1.x); F2(acc[(O)*4+3],cv67,q1.y); \
    F2(acc[(O)*4+4],cv01,q0.y); F2(acc[(O)*4+5],cv23,q1.x); F2(acc[(O)*4+6],cv45,q1.y); F2(acc[(O)*4+7],cv67,q2.x); \
    F2(acc[(O)*4+8],cv01,q1.x); F2(acc[(O)*4+9],cv23,q1.y); F2(acc[(O)*4+10],cv45,q2.x); F2(acc[(O)*4+11],cv67,q2.y); \
    F2(acc[(O)*4+12],cv01,q1.y); F2(acc[(O)*4+13],cv23,q2.x); F2(acc[(O)*4+14],cv45,q2.y); F2(acc[(O)*4+15],cv67,q3.x); \
    F2(acc[(O)*4+16],cv01,q2.x); F2(acc[(O)*4+17],cv23,q2.y); F2(acc[(O)*4+18],cv45,q3.x); F2(acc[(O)*4+19],cv67,q3.y); \
} while (0)

#define MROW(O, RB) do { \
    const unsigned f3 = *(const unsigned*)((RB) + 12); \
    const ulonglong2 q1 = LD2((RB) + 16), q2 = LD2((RB) + 32); \
    const unsigned f12 = *(const unsigned*)((RB) + 48); \
    const u64 P34 = PK(f3, LOW(q1.x)),      P56 = PK(HIW(q1.x), LOW(q1.y)); \
    const u64 P78 = PK(HIW(q1.y), LOW(q2.x)), P9A = PK(HIW(q2.x), LOW(q2.y)); \
    const u64 PBC = PK(HIW(q2.y), f12); \
    F2(acc[(O)*4+0],cv01,P34);  F2(acc[(O)*4+1],cv23,P56);  F2(acc[(O)*4+2],cv45,P78);  F2(acc[(O)*4+3],cv67,P9A); \
    F2(acc[(O)*4+4],cv01,q1.x); F2(acc[(O)*4+5],cv23,q1.y); F2(acc[(O)*4+6],cv45,q2.x); F2(acc[(O)*4+7],cv67,q2.y); \
    F2(acc[(O)*4+8],cv01,P56);  F2(acc[(O)*4+9],cv23,P78);  F2(acc[(O)*4+10],cv45,P9A); F2(acc[(O)*4+11],cv67,PBC); \
} while (0)

#define PREAMBLE \
    const char* secB = pbuf + cc * PSEC; \
    const char* rowB = secB + tyOff; \
    const char* cvP  = cbuf + cc * CSEC + cvOff; \
    const ulonglong2 CA = LD2(cvP), CB = LD2(cvP + 16); \
    const u64 cv01 = CA.x, cv23 = CA.y, cv45 = CB.x, cv67 = CB.y;

    #pragma unroll 1
    for (int k = 0; k < NCHUNK; k++) {
        if (k < NCHUNK - 1) asm volatile("cp.async.wait_group 1;\n" ::: "memory");
        else                asm volatile("cp.async.wait_group 0;\n" ::: "memory");
        __syncthreads();

        if (k < NCHUNK - 2) {
            issue(srcPs, srcCs, smA + SM_PREV + bS * PREV_BUF, smA + SM_CURR + bS * CURR_BUF);
            srcPs += (size_t)CHUNK * PLANE * 4;
            srcCs += (size_t)CHUNK * PLANE * 4;
            bS = (bS == 2) ? 0 : bS + 1;
        }

        const char* pbuf = smem + SM_PREV + bC * PREV_BUF;
        const char* cbuf = smem + SM_CURR + bC * CURR_BUF;

        if (grp == 0) {
            #pragma unroll
            for (int cc = 0; cc < CHUNK; cc++) {
                PREAMBLE
                F2(aux[0], cv01, cv01); F2(aux[1], cv23, cv23);   // ssq
                F2(aux[2], cv45, cv45); F2(aux[3], cv67, cv67);
                FROW(0, rowB);                      // dy=-4: o0..4
                MROW(5, rowB + 528);                // dy=-1: o10..12
                const u64 p01 = LD1(rowB + 1056);   // o23 pair01
                F2(acc[32], cv01, p01);
            }
        } else if (grp == 1) {
            #pragma unroll
            for (int cc = 0; cc < CHUNK; cc++) {
                PREAMBLE
                if (doFB) { const ulonglong2 v = LD2(secB + fbOff); F2(aux[0], v.x, v.x); F2(aux[1], v.y, v.y); }
                FROW(0, rowB + 352);                // dy=-2: o5..9
                MROW(5, rowB + 880);                // dy=+1: o20..22
            }
        } else if (grp == 2) {
            #pragma unroll
            for (int cc = 0; cc < CHUNK; cc++) {
                PREAMBLE
                {   // dy=0: o13..19 + interior prev-sq (aux)
                    const char* rb = rowB + 704;
                    const ulonglong2 q0 = LD2(rb), q1 = LD2(rb + 16), q2 = LD2(rb + 32), q3 = LD2(rb + 48);
                    F2(aux[0], q1.x, q1.x); F2(aux[1], q1.y, q1.y);
                    F2(aux[2], q2.x, q2.x); F2(aux[3], q2.y, q2.y);
                    const u64 P34 = PK(HIW(q0.y), LOW(q1.x)), P56 = PK(HIW(q1.x), LOW(q1.y));
                    const u64 P78 = PK(HIW(q1.y), LOW(q2.x)), P9A = PK(HIW(q2.x), LOW(q2.y));
                    const u64 PBC = PK(HIW(q2.y), LOW(q3.x));
                    F2(acc[0],cv01,q0.x);  F2(acc[1],cv23,q0.y);  F2(acc[2],cv45,q1.x);  F2(acc[3],cv67,q1.y);
                    F2(acc[4],cv01,q0.y);  F2(acc[5],cv23,q1.x);  F2(acc[6],cv45,q1.y);  F2(acc[7],cv67,q2.x);
                    F2(acc[8],cv01,P34);   F2(acc[9],cv23,P56);   F2(acc[10],cv45,P78);  F2(acc[11],cv67,P9A);
                    F2(acc[12],cv01,q1.x); F2(acc[13],cv23,q1.y); F2(acc[14],cv45,q2.x); F2(acc[15],cv67,q2.y);
                    F2(acc[16],cv01,P56);  F2(acc[17],cv23,P78);  F2(acc[18],cv45,P9A);  F2(acc[19],cv67,PBC);
                    F2(acc[20],cv01,q1.y); F2(acc[21],cv23,q2.x); F2(acc[22],cv45,q2.y); F2(acc[23],cv67,q3.x);
                    F2(acc[24],cv01,q2.x); F2(acc[25],cv23,q2.y); F2(acc[26],cv45,q3.x); F2(acc[27],cv67,q3.y);
                }
                {   // dy=+2: o24 (dx-2) + o23 pair23
                    const char* rb6 = rowB + 1056;
                    const u64 d23 = LD1(rb6 + 8);
                    const ulonglong2 m = LD2(rb6 + 16);
                    const u64 d89 = LD1(rb6 + 32);
                    F2(acc[28],cv01,d23); F2(acc[29],cv23,m.x); F2(acc[30],cv45,m.y); F2(acc[31],cv67,d89);
                    F2(acc[32], cv23, d23);
                }
            }
        } else {
            #pragma unroll
            for (int cc = 0; cc < CHUNK; cc++) {
                PREAMBLE
                if (doFB) { const ulonglong2 v = LD2(secB + fbOff); F2(aux[0], v.x, v.x); F2(aux[1], v.y, v.y); }
                FROW(0, rowB + 1408);               // dy=+4: o28..32
                {   // dy=+2 dx{0,2,4}: o25..o27 + o23 pairs45/67
                    const char* rb = rowB + 1056;
                    const ulonglong2 q1 = LD2(rb + 16), q2 = LD2(rb + 32), q3 = LD2(rb + 48);
                    F2(acc[20],cv01,q1.x); F2(acc[21],cv23,q1.y); F2(acc[22],cv45,q2.x); F2(acc[23],cv67,q2.y);
                    F2(acc[24],cv01,q1.y); F2(acc[25],cv23,q2.x); F2(acc[26],cv45,q2.y); F2(acc[27],cv67,q3.x);
                    F2(acc[28],cv01,q2.x); F2(acc[29],cv23,q2.y); F2(acc[30],cv45,q3.x); F2(acc[31],cv67,q3.y);
                    F2(acc[32], cv45, q1.x);
                    F2(acc[33], cv67, q1.y);
                }
            }
        }
        bC = (bC == 2) ? 0 : bC + 1;
    }

    // ---- cross-CTA combine: first arriver dumps, second finalizes ----
    __syncthreads();
    if (tid == 0) {
        const unsigned old = atomicAdd(&g_cnt[tileId], 1u);
        ((unsigned*)(smem + SM_FLAG))[0] = old;
    }
    __syncthreads();
    const unsigned old = ((volatile unsigned*)(smem + SM_FLAG))[0];

    if ((old & 1u) == 0u) {
        // first arriver: dump raw partials, signal, exit
        u64* dA = g_acc + (size_t)tileId * 34 * 256 + tid;
        #pragma unroll
        for (int i = 0; i < 34; i++) dA[i * 256] = acc[i];
        u64* dX = g_aux + (size_t)tileId * 4 * 256 + tid;
        #pragma unroll
        for (int i = 0; i < 4; i++) dX[i * 256] = aux[i];
        __threadfence();
        __syncthreads();
        if (tid == 0) atomicAdd(&g_rdy[tileId], 1u);
        return;
    }

    // second arriver: wait for partner dump (bounded spin; partner is resident)
    {
        const unsigned want = (old >> 1) + 1u;
        if (tid == 0) {
            while (atomicAdd(&g_rdy[tileId], 0u) < want) { }
        }
        __syncthreads();
        __threadfence();
        const u64* sA = g_acc + (size_t)tileId * 34 * 256 + tid;
        #pragma unroll
        for (int i = 0; i < 34; i++) ADD2(acc[i], __ldcg(sA + i * 256));
        const u64* sX = g_aux + (size_t)tileId * 4 * 256 + tid;
        #pragma unroll
        for (int i = 0; i < 4; i++) ADD2(aux[i], __ldcg(sX + i * 256));
    }

    // ---- epilogue: norms into smem ----
    {
        char* sspB = smem + SM_SSP;
        if (grp == 0) {
            float4 c0, c1;
            c0.x = rsqrtf(FL(aux[0])); c0.y = rsqrtf(FH(aux[0]));
            c0.z = rsqrtf(FL(aux[1])); c0.w = rsqrtf(FH(aux[1]));
            c1.x = rsqrtf(FL(aux[2])); c1.y = rsqrtf(FH(aux[2]));
            c1.z = rsqrtf(FL(aux[3])); c1.w = rsqrtf(FH(aux[3]));
            char* cdst = smem + SM_CIV + ty * CROW + xg * 32;
            *(float4*)cdst = c0;
            *(float4*)(cdst + 16) = c1;
        } else if (grp == 2) {
            float4 w0, w1;
            w0.x = GRD(FL(aux[0])); w0.y = GRD(FH(aux[0]));
            w0.z = GRD(FL(aux[1])); w0.w = GRD(FH(aux[1]));
            w1.x = GRD(FL(aux[2])); w1.y = GRD(FH(aux[2]));
            w1.z = GRD(FL(aux[3])); w1.w = GRD(FH(aux[3]));
            char* dst = sspB + (ty + 4) * HROW + xg * 32 + 16;
            *(float4*)dst = w0;
            *(float4*)(dst + 16) = w1;
        }
        if (doFB) {
            float4 w;
            w.x = GRD(FL(aux[0])); w.y = GRD(FH(aux[0]));
            w.z = GRD(FL(aux[1])); w.w = GRD(FH(aux[1]));
            *(float4*)(sspB + fbOff) = w;
        }
    }
    __syncthreads();

    u64 inv01, inv23, inv45, inv67;
    {
        const char* civ = smem + SM_CIV + ty * CROW + xg * 32;
        const ulonglong2 IA = LD2(civ), IB = LD2(civ + 16);
        inv01 = IA.x; inv23 = IA.y; inv45 = IB.x; inv67 = IB.y;
    }

    const char* srow = smem + SM_SSP + tyOff;
    char* outBase = (char*)(out + ((size_t)bb * 33 * HH + (y0 + ty)) * WW + x0 + xg * 8);

#define OST(PL, O, B0, B1, B2, B3) do { \
    ulonglong2 r0, r1; \
    r0.x = M2(M2(acc[(O)*4+0], inv01), (B0)); \
    r0.y = M2(M2(acc[(O)*4+1], inv23), (B1)); \
    r1.x = M2(M2(acc[(O)*4+2], inv45), (B2)); \
    r1.y = M2(M2(acc[(O)*4+3], inv67), (B3)); \
    char* _op = outBase + (size_t)(PL) * (PLANE * 4); \
    *(ulonglong2*)_op = r0; \
    *(ulonglong2*)(_op + 16) = r1; \
} while (0)

#define EFROW(SR, PL, O) do { \
    const ulonglong2 q0 = LD2(srow + (SR)), q1 = LD2(srow + (SR) + 16); \
    const ulonglong2 q2 = LD2(srow + (SR) + 32), q3 = LD2(srow + (SR) + 48); \
    OST((PL)+0, (O)+0, q0.x, q0.y, q1.x, q1.y); \
    OST((PL)+1, (O)+1, q0.y, q1.x, q1.y, q2.x); \
    OST((PL)+2, (O)+2, q1.x, q1.y, q2.x, q2.y); \
    OST((PL)+3, (O)+3, q1.y, q2.x, q2.y, q3.x); \
    OST((PL)+4, (O)+4, q2.x, q2.y, q3.x, q3.y); \
} while (0)

#define EMROW(SR, PL, O) do { \
    const unsigned f3 = *(const unsigned*)(srow + (SR) + 12); \
    const ulonglong2 q1 = LD2(srow + (SR) + 16), q2 = LD2(srow + (SR) + 32); \
    const unsigned f12 = *(const unsigned*)(srow + (SR) + 48); \
    const u64 P34 = PK(f3, LOW(q1.x)),        P56 = PK(HIW(q1.x), LOW(q1.y)); \
    const u64 P78 = PK(HIW(q1.y), LOW(q2.x)), P9A = PK(HIW(q2.x), LOW(q2.y)); \
    const u64 PBC = PK(HIW(q2.y), f12); \
    OST((PL)+0, (O)+0, P34, P56, P78, P9A); \
    OST((PL)+1, (O)+1, q1.x, q1.y, q2.x, q2.y); \
    OST((PL)+2, (O)+2, P56, P78, P9A, PBC); \
} while (0)

    char* o23base = outBase + (size_t)23 * (PLANE * 4);

    if (grp == 0) {
        EFROW(0, 0, 0);        // dy=-4: o0..4
        EMROW(528, 10, 5);     // dy=-1: o10..12
        {                      // o23 pixels 0,1
            const u64 n01 = LD1(srow + 1056);
            *(u64*)o23base = M2(M2(acc[32], inv01), n01);
        }
    } else if (grp == 1) {
        EFROW(352, 5, 0);      // dy=-2: o5..9
        EMROW(880, 20, 5);     // dy=+1: o20..22
    } else if (grp == 2) {
        {   // dy=0: o13..19
            const ulonglong2 q0 = LD2(srow + 704), q1 = LD2(srow + 720);
            const ulonglong2 q2 = LD2(srow + 736), q3 = LD2(srow + 752);
            const u64 P34 = PK(HIW(q0.y), LOW(q1.x)), P56 = PK(HIW(q1.x), LOW(q1.y));
            const u64 P78 = PK(HIW(q1.y), LOW(q2.x)), P9A = PK(HIW(q2.x), LOW(q2.y));
            const u64 PBC = PK(HIW(q2.y), LOW(q3.x));
            OST(13, 0, q0.x, q0.y, q1.x, q1.y);
            OST(14, 1, q0.y, q1.x, q1.y, q2.x);
            OST(15, 2, P34, P56, P78, P9A);
            OST(16, 3, q1.x, q1.y, q2.x, q2.y);
            OST(17, 4, P56, P78, P9A, PBC);
            OST(18, 5, q1.y, q2.x, q2.y, q3.x);
            OST(19, 6, q2.x, q2.y, q3.x, q3.y);
        }
        {   // o24 (dy+2, dx-2) + o23 pixels 2,3
            const u64 nd23 = LD1(srow + 1064);
            const ulonglong2 nm = LD2(srow + 1072);
            const u64 nd89 = LD1(srow + 1088);
            OST(24, 7, nd23, nm.x, nm.y, nd89);
            *(u64*)(o23base + 8) = M2(M2(acc[32], inv23), nd23);
        }
    } else {
        EFROW(1408, 28, 0);    // dy=+4: o28..32
        {   // dy=+2 dx{0,2,4}: o25..o27 + o23 pixels 4..7
            const ulonglong2 t1 = LD2(srow + 1072), t2 = LD2(srow + 1088), t3 = LD2(srow + 1104);
            OST(25, 5, t1.x, t1.y, t2.x, t2.y);
            OST(26, 6, t1.y, t2.x, t2.y, t3.x);
            OST(27, 7, t2.x, t2.y, t3.x, t3.y);
            *(u64*)(o23base + 16) = M2(M2(acc[32], inv45), t1.x);
            *(u64*)(o23base + 24) = M2(M2(acc[33], inv67), t1.y);
        }
    }
}

extern "C" void kernel_launch(void* const* d_in, const int* in_sizes, int n_in,
                              void* d_out, int out_size)
{
    const float* curr = (const float*)d_in[0];
    const float* prev = (const float*)d_in[1];
    float* out = (float*)d_out;

    cudaFuncSetAttribute(corr_kernel, cudaFuncAttributeMaxDynamicSharedMemorySize, SMEM_BYTES);

    dim3 grid(WW / TILE_W, HH / TILE_H, BB * 2);   // 6 x 8 x 16 = 768 half-CTAs
    corr_kernel<<<grid, NT, SMEM_BYTES>>>(curr, prev, out);
}

// round 16
// speedup vs baseline: 1.0120x; 1.0120x over previous
#include <cuda_runtime.h>
#include <cstdint>

#define HH 128
#define WW 192
#define CC_TOT 256
#define C_HALF 128
#define BB 8
#define TILE_W 32
#define TILE_H 16
#define HALO_H 24
#define CHUNK 4
#define NCHUNK (C_HALF / CHUNK)           // 32 per half-CTA
#define NT 256
#define PLANE ((size_t)HH * WW)
#define NTILE 384

#define HROW 176
#define CROW 144
#define PSEC (HALO_H * HROW)              // 4224
#define CSEC (TILE_H * CROW)              // 2304
#define PREV_BUF (CHUNK * PSEC)           // 16896
#define CURR_BUF (CHUNK * CSEC)           // 9216
#define SM_PREV 0
#define SM_CURR (3 * PREV_BUF)            // 50688
#define SM_SSP  (SM_CURR + 3 * CURR_BUF)  // 78336
#define SM_CIV  (SM_SSP + PSEC)           // 82560
#define SM_FLAG (SM_CIV + CSEC)           // 84864
#define SMEM_BYTES (SM_FLAG + 16)         // 84880 -> 2 CTAs/SM

typedef unsigned long long u64;

// cross-CTA combine scratch (zero-initialized; counter monotonic => parity-safe under graph replay)
__device__ u64 g_acc[(size_t)NTILE * 2 * 34 * 256];
__device__ u64 g_aux[(size_t)NTILE * 2 * 4 * 256];
__device__ unsigned int g_cnt[NTILE];

__device__ __forceinline__ void F2(u64 &d, u64 a, u64 b) {
    asm("fma.rn.f32x2 %0, %1, %2, %0;" : "+l"(d) : "l"(a), "l"(b));
}
__device__ __forceinline__ void ADD2(u64 &d, u64 a) {
    asm("add.rn.f32x2 %0, %0, %1;" : "+l"(d) : "l"(a));
}
__device__ __forceinline__ u64 M2(u64 a, u64 b) {
    u64 d; asm("mul.rn.f32x2 %0, %1, %2;" : "=l"(d) : "l"(a), "l"(b)); return d;
}
__device__ __forceinline__ u64 PK(unsigned a, unsigned b) {
    u64 d; asm("mov.b64 %0, {%1, %2};" : "=l"(d) : "r"(a), "r"(b)); return d;
}
__device__ __forceinline__ unsigned LOW(u64 a) {
    unsigned l, h; asm("mov.b64 {%0, %1}, %2;" : "=r"(l), "=r"(h) : "l"(a)); return l;
}
__device__ __forceinline__ unsigned HIW(u64 a) {
    unsigned l, h; asm("mov.b64 {%0, %1}, %2;" : "=r"(l), "=r"(h) : "l"(a)); return h;
}
__device__ __forceinline__ float FL(u64 a) { return __uint_as_float(LOW(a)); }
__device__ __forceinline__ float FH(u64 a) { return __uint_as_float(HIW(a)); }
__device__ __forceinline__ void cp16(uint32_t dst, const void* src, int szbytes) {
    asm volatile("cp.async.cg.shared.global [%0], [%1], 16, %2;\n"
                 :: "r"(dst), "l"(src), "r"(szbytes) : "memory");
}
__device__ __forceinline__ ulonglong2 LD2(const void* p) {
    return *reinterpret_cast<const ulonglong2*>(p);
}
__device__ __forceinline__ u64 LD1(const void* p) {
    return *reinterpret_cast<const u64*>(p);
}
__device__ __forceinline__ float GRD(float v) { return v > 0.f ? rsqrtf(v) : 0.f; }

__global__ void __launch_bounds__(NT, 2)
corr_kernel(const float* __restrict__ curr, const float* __restrict__ prev,
            float* __restrict__ out)
{
    extern __shared__ char smem[];

    const int tid = threadIdx.x;
    const int grp = tid >> 6;          // 4 groups of 64 threads
    const int gt  = tid & 63;
    const int xg  = gt & 3;            // 4 x-groups of 8 pixels
    const int ty  = gt >> 2;           // 16 rows
    const int x0  = blockIdx.x * TILE_W;
    const int y0  = blockIdx.y * TILE_H;
    const int tz  = blockIdx.z;
    const int half = tz & 1;
    const int bb  = tz >> 1;
    const int tileId = bb * 48 + blockIdx.y * 6 + blockIdx.x;

    const char* currB = (const char*)(curr + ((size_t)bb * CC_TOT + (size_t)half * C_HALF) * PLANE);
    const char* prevB = (const char*)(prev + ((size_t)bb * CC_TOT + (size_t)half * C_HALF) * PLANE);
    const uint32_t smA = (uint32_t)__cvta_generic_to_shared(smem);

    // ---- staging precompute ----
    const int psy = tid / 10, psx = tid - psy * 10;   // 240 prev f4 slots
    const int pgy = y0 - 4 + psy, pgx = x0 - 4 + psx * 4;
    const bool doP = (tid < 240);
    const bool pok = doP && ((unsigned)pgy < HH) && ((unsigned)pgx < WW);
    const int pOff = pok ? (pgy * WW + pgx) * 4 : 0;
    const int psz  = pok ? 16 : 0;
    const uint32_t pRel = (uint32_t)(psy * HROW + psx * 16);
    const bool doC = (tid >= 128);
    const int cslot = tid - 128;
    const int csy = cslot >> 3, csx = cslot & 7;
    const int cOff = ((y0 + csy) * WW + x0 + csx * 4) * 4;
    const uint32_t cRel = (uint32_t)(csy * CROW + csx * 16);

    // ---- boundary prev-sq: 112 slots on G1(56)/G3(56) ----
    int fbj = -1;
    if (grp == 1)      { if (gt < 56) fbj = gt; }
    else if (grp == 3) { if (gt < 56) fbj = 56 + gt; }
    const bool doFB = (fbj >= 0);
    int fbRow = 0, fbCol = 0;
    if (fbj >= 0) {
        if (fbj < 40)      { fbRow = fbj / 10; fbCol = fbj - fbRow * 10; }
        else if (fbj < 80) { int i = fbj - 40; fbRow = 20 + i / 10; fbCol = i - (i / 10) * 10; }
        else               { int i = fbj - 80; fbRow = 4 + (i >> 1); fbCol = (i & 1) ? 9 : 0; }
    }
    const uint32_t fbOff = (uint32_t)(fbRow * HROW + fbCol * 16);

    // ---- accumulators (layout as R12) ----
    u64 acc[34];
    #pragma unroll
    for (int i = 0; i < 34; i++) acc[i] = 0ull;
    u64 aux[4];
    #pragma unroll
    for (int i = 0; i < 4; i++) aux[i] = 0ull;

    auto issue = [&](const char* srcP, const char* srcC, uint32_t dP, uint32_t dC) {
        #pragma unroll
        for (int cc = 0; cc < CHUNK; cc++) {
            const size_t so = (size_t)cc * PLANE * 4;
            if (doP) cp16(dP + cc * PSEC + pRel, srcP + so + pOff, psz);
            if (doC) cp16(dC + cc * CSEC + cRel, srcC + so + cOff, 16);
        }
        asm volatile("cp.async.commit_group;\n" ::: "memory");
    };

    issue(prevB, currB, smA + SM_PREV, smA + SM_CURR);
    issue(prevB + (size_t)CHUNK * PLANE * 4, currB + (size_t)CHUNK * PLANE * 4,
          smA + SM_PREV + PREV_BUF, smA + SM_CURR + CURR_BUF);

    const char* srcPs = prevB + (size_t)2 * CHUNK * PLANE * 4;
    const char* srcCs = currB + (size_t)2 * CHUNK * PLANE * 4;
    int bC = 0, bS = 2;

    const int tyOff = ty * HROW + xg * 32;
    const int cvOff = ty * CROW + xg * 32;

#define FROW(O, RB) do { \
    const ulonglong2 q0 = LD2(RB), q1 = LD2((RB) + 16), q2 = LD2((RB) + 32), q3 = LD2((RB) + 48); \
    F2(acc[(O)*4+0],cv01,q0.x); F2(acc[(O)*4+1],cv23,q0.y); F2(acc[(O)*4+2],cv45,q1.x); F2(acc[(O)*4+3],cv67,q1.y); \
    F2(acc[(O)*4+4],cv01,q0.y); F2(acc[(O)*4+5],cv23,q1.x); F2(acc[(O)*4+6],cv45,q1.y); F2(acc[(O)*4+7],cv67,q2.x); \
    F2(acc[(O)*4+8],cv01,q1.x); F2(acc[(O)*4+9],cv23,q1.y); F2(acc[(O)*4+10],cv45,q2.x); F2(acc[(O)*4+11],cv67,q2.y); \
    F2(acc[(O)*4+12],cv01,q1.y); F2(acc[(O)*4+13],cv23,q2.x); F2(acc[(O)*4+14],cv45,q2.y); F2(acc[(O)*4+15],cv67,q3.x); \
    F2(acc[(O)*4+16],cv01,q2.x); F2(acc[(O)*4+17],cv23,q2.y); F2(acc[(O)*4+18],cv45,q3.x); F2(acc[(O)*4+19],cv67,q3.y); \
} while (0)

#define MROW(O, RB) do { \
    const unsigned f3 = *(const unsigned*)((RB) + 12); \
    const ulonglong2 q1 = LD2((RB) + 16), q2 = LD2((RB) + 32); \
    const unsigned f12 = *(const unsigned*)((RB) + 48); \
    const u64 P34 = PK(f3, LOW(q1.x)),      P56 = PK(HIW(q1.x), LOW(q1.y)); \
    const u64 P78 = PK(HIW(q1.y), LOW(q2.x)), P9A = PK(HIW(q2.x), LOW(q2.y)); \
    const u64 PBC = PK(HIW(q2.y), f12); \
    F2(acc[(O)*4+0],cv01,P34);  F2(acc[(O)*4+1],cv23,P56);  F2(acc[(O)*4+2],cv45,P78);  F2(acc[(O)*4+3],cv67,P9A); \
    F2(acc[(O)*4+4],cv01,q1.x); F2(acc[(O)*4+5],cv23,q1.y); F2(acc[(O)*4+6],cv45,q2.x); F2(acc[(O)*4+7],cv67,q2.y); \
    F2(acc[(O)*4+8],cv01,P56);  F2(acc[(O)*4+9],cv23,P78);  F2(acc[(O)*4+10],cv45,P9A); F2(acc[(O)*4+11],cv67,PBC); \
} while (0)

#define PREAMBLE \
    const char* secB = pbuf + cc * PSEC; \
    const char* rowB = secB + tyOff; \
    const char* cvP  = cbuf + cc * CSEC + cvOff; \
    const ulonglong2 CA = LD2(cvP), CB = LD2(cvP + 16); \
    const u64 cv01 = CA.x, cv23 = CA.y, cv45 = CB.x, cv67 = CB.y;

    #pragma unroll 1
    for (int k = 0; k < NCHUNK; k++) {
        if (k < NCHUNK - 1) asm volatile("cp.async.wait_group 1;\n" ::: "memory");
        else                asm volatile("cp.async.wait_group 0;\n" ::: "memory");
        __syncthreads();

        if (k < NCHUNK - 2) {
            issue(srcPs, srcCs, smA + SM_PREV + bS * PREV_BUF, smA + SM_CURR + bS * CURR_BUF);
            srcPs += (size_t)CHUNK * PLANE * 4;
            srcCs += (size_t)CHUNK * PLANE * 4;
            bS = (bS == 2) ? 0 : bS + 1;
        }

        const char* pbuf = smem + SM_PREV + bC * PREV_BUF;
        const char* cbuf = smem + SM_CURR + bC * CURR_BUF;

        if (grp == 0) {
            #pragma unroll
            for (int cc = 0; cc < CHUNK; cc++) {
                PREAMBLE
                F2(aux[0], cv01, cv01); F2(aux[1], cv23, cv23);   // ssq
                F2(aux[2], cv45, cv45); F2(aux[3], cv67, cv67);
                FROW(0, rowB);                      // dy=-4: o0..4
                MROW(5, rowB + 528);                // dy=-1: o10..12
                const u64 p01 = LD1(rowB + 1056);   // o23 pair01
                F2(acc[32], cv01, p01);
            }
        } else if (grp == 1) {
            #pragma unroll
            for (int cc = 0; cc < CHUNK; cc++) {
                PREAMBLE
                if (doFB) { const ulonglong2 v = LD2(secB + fbOff); F2(aux[0], v.x, v.x); F2(aux[1], v.y, v.y); }
                FROW(0, rowB + 352);                // dy=-2: o5..9
                MROW(5, rowB + 880);                // dy=+1: o20..22
            }
        } else if (grp == 2) {
            #pragma unroll
            for (int cc = 0; cc < CHUNK; cc++) {
                PREAMBLE
                {   // dy=0: o13..19 + interior prev-sq (aux)
                    const char* rb = rowB + 704;
                    const ulonglong2 q0 = LD2(rb), q1 = LD2(rb + 16), q2 = LD2(rb + 32), q3 = LD2(rb + 48);
                    F2(aux[0], q1.x, q1.x); F2(aux[1], q1.y, q1.y);
                    F2(aux[2], q2.x, q2.x); F2(aux[3], q2.y, q2.y);
                    const u64 P34 = PK(HIW(q0.y), LOW(q1.x)), P56 = PK(HIW(q1.x), LOW(q1.y));
                    const u64 P78 = PK(HIW(q1.y), LOW(q2.x)), P9A = PK(HIW(q2.x), LOW(q2.y));
                    const u64 PBC = PK(HIW(q2.y), LOW(q3.x));
                    F2(acc[0],cv01,q0.x);  F2(acc[1],cv23,q0.y);  F2(acc[2],cv45,q1.x);  F2(acc[3],cv67,q1.y);
                    F2(acc[4],cv01,q0.y);  F2(acc[5],cv23,q1.x);  F2(acc[6],cv45,q1.y);  F2(acc[7],cv67,q2.x);
                    F2(acc[8],cv01,P34);   F2(acc[9],cv23,P56);   F2(acc[10],cv45,P78);  F2(acc[11],cv67,P9A);
                    F2(acc[12],cv01,q1.x); F2(acc[13],cv23,q1.y); F2(acc[14],cv45,q2.x); F2(acc[15],cv67,q2.y);
                    F2(acc[16],cv01,P56);  F2(acc[17],cv23,P78);  F2(acc[18],cv45,P9A);  F2(acc[19],cv67,PBC);
                    F2(acc[20],cv01,q1.y); F2(acc[21],cv23,q2.x); F2(acc[22],cv45,q2.y); F2(acc[23],cv67,q3.x);
                    F2(acc[24],cv01,q2.x); F2(acc[25],cv23,q2.y); F2(acc[26],cv45,q3.x); F2(acc[27],cv67,q3.y);
                }
                {   // dy=+2: o24 (dx-2) + o23 pair23
                    const char* rb6 = rowB + 1056;
                    const u64 d23 = LD1(rb6 + 8);
                    const ulonglong2 m = LD2(rb6 + 16);
                    const u64 d89 = LD1(rb6 + 32);
                    F2(acc[28],cv01,d23); F2(acc[29],cv23,m.x); F2(acc[30],cv45,m.y); F2(acc[31],cv67,d89);
                    F2(acc[32], cv23, d23);
                }
            }
        } else {
            #pragma unroll
            for (int cc = 0; cc < CHUNK; cc++) {
                PREAMBLE
                if (doFB) { const ulonglong2 v = LD2(secB + fbOff); F2(aux[0], v.x, v.x); F2(aux[1], v.y, v.y); }
                FROW(0, rowB + 1408);               // dy=+4: o28..32
                {   // dy=+2 dx{0,2,4}: o25..o27 + o23 pairs45/67
                    const char* rb = rowB + 1056;
                    const ulonglong2 q1 = LD2(rb + 16), q2 = LD2(rb + 32), q3 = LD2(rb + 48);
                    F2(acc[20],cv01,q1.x); F2(acc[21],cv23,q1.y); F2(acc[22],cv45,q2.x); F2(acc[23],cv67,q2.y);
                    F2(acc[24],cv01,q1.y); F2(acc[25],cv23,q2.x); F2(acc[26],cv45,q2.y); F2(acc[27],cv67,q3.x);
                    F2(acc[28],cv01,q2.x); F2(acc[29],cv23,q2.y); F2(acc[30],cv45,q3.x); F2(acc[31],cv67,q3.y);
                    F2(acc[32], cv45, q1.x);
                    F2(acc[33], cv67, q1.y);
                }
            }
        }
        bC = (bC == 2) ? 0 : bC + 1;
    }

    // ---- cross-CTA combine: wait-free both-dump; parity names the finalizer ----
    {
        const size_t slot = (size_t)tileId * 2 + half;
        u64* dA = g_acc + slot * 34 * 256 + tid;
        #pragma unroll
        for (int i = 0; i < 34; i++) dA[i * 256] = acc[i];
        u64* dX = g_aux + slot * 4 * 256 + tid;
        #pragma unroll
        for (int i = 0; i < 4; i++) dX[i * 256] = aux[i];
    }
    __threadfence();
    __syncthreads();
    if (tid == 0) {
        const unsigned old = atomicAdd(&g_cnt[tileId], 1u);
        *(int*)(smem + SM_FLAG) = (int)(old & 1u);
    }
    __syncthreads();
    if (*(volatile int*)(smem + SM_FLAG) == 0) return;   // first arriver: partner finalizes
    __threadfence();

    // second arriver: combine partner half (its dump happened-before its atomic)
    {
        const size_t slot = (size_t)tileId * 2 + (half ^ 1);
        const u64* sA = g_acc + slot * 34 * 256 + tid;
        #pragma unroll
        for (int i = 0; i < 34; i++) ADD2(acc[i], __ldcg(sA + i * 256));
        const u64* sX = g_aux + slot * 4 * 256 + tid;
        #pragma unroll
        for (int i = 0; i < 4; i++) ADD2(aux[i], __ldcg(sX + i * 256));
    }

    // ---- epilogue: norms into smem ----
    {
        char* sspB = smem + SM_SSP;
        if (grp == 0) {
            float4 c0, c1;
            c0.x = rsqrtf(FL(aux[0])); c0.y = rsqrtf(FH(aux[0]));
            c0.z = rsqrtf(FL(aux[1])); c0.w = rsqrtf(FH(aux[1]));
            c1.x = rsqrtf(FL(aux[2])); c1.y = rsqrtf(FH(aux[2]));
            c1.z = rsqrtf(FL(aux[3])); c1.w = rsqrtf(FH(aux[3]));
            char* cdst = smem + SM_CIV + ty * CROW + xg * 32;
            *(float4*)cdst = c0;
            *(float4*)(cdst + 16) = c1;
        } else if (grp == 2) {
            float4 w0, w1;
            w0.x = GRD(FL(aux[0])); w0.y = GRD(FH(aux[0]));
            w0.z = GRD(FL(aux[1])); w0.w = GRD(FH(aux[1]));
            w1.x = GRD(FL(aux[2])); w1.y = GRD(FH(aux[2]));
            w1.z = GRD(FL(aux[3])); w1.w = GRD(FH(aux[3]));
            char* dst = sspB + (ty + 4) * HROW + xg * 32 + 16;
            *(float4*)dst = w0;
            *(float4*)(dst + 16) = w1;
        }
        if (doFB) {
            float4 w;
            w.x = GRD(FL(aux[0])); w.y = GRD(FH(aux[0]));
            w.z = GRD(FL(aux[1])); w.w = GRD(FH(aux[1]));
            *(float4*)(sspB + fbOff) = w;
        }
    }
    __syncthreads();

    u64 inv01, inv23, inv45, inv67;
    {
        const char* civ = smem + SM_CIV + ty * CROW + xg * 32;
        const ulonglong2 IA = LD2(civ), IB = LD2(civ + 16);
        inv01 = IA.x; inv23 = IA.y; inv45 = IB.x; inv67 = IB.y;
    }

    const char* srow = smem + SM_SSP + tyOff;
    char* outBase = (char*)(out + ((size_t)bb * 33 * HH + (y0 + ty)) * WW + x0 + xg * 8);

#define OST(PL, O, B0, B1, B2, B3) do { \
    ulonglong2 r0, r1; \
    r0.x = M2(M2(acc[(O)*4+0], inv01), (B0)); \
    r0.y = M2(M2(acc[(O)*4+1], inv23), (B1)); \
    r1.x = M2(M2(acc[(O)*4+2], inv45), (B2)); \
    r1.y = M2(M2(acc[(O)*4+3], inv67), (B3)); \
    char* _op = outBase + (size_t)(PL) * (PLANE * 4); \
    *(ulonglong2*)_op = r0; \
    *(ulonglong2*)(_op + 16) = r1; \
} while (0)

#define EFROW(SR, PL, O) do { \
    const ulonglong2 q0 = LD2(srow + (SR)), q1 = LD2(srow + (SR) + 16); \
    const ulonglong2 q2 = LD2(srow + (SR) + 32), q3 = LD2(srow + (SR) + 48); \
    OST((PL)+0, (O)+0, q0.x, q0.y, q1.x, q1.y); \
    OST((PL)+1, (O)+1, q0.y, q1.x, q1.y, q2.x); \
    OST((PL)+2, (O)+2, q1.x, q1.y, q2.x, q2.y); \
    OST((PL)+3, (O)+3, q1.y, q2.x, q2.y, q3.x); \
    OST((PL)+4, (O)+4, q2.x, q2.y, q3.x, q3.y); \
} while (0)

#define EMROW(SR, PL, O) do { \
    const unsigned f3 = *(const unsigned*)(srow + (SR) + 12); \
    const ulonglong2 q1 = LD2(srow + (SR) + 16), q2 = LD2(srow + (SR) + 32); \
    const unsigned f12 = *(const unsigned*)(srow + (SR) + 48); \
    const u64 P34 = PK(f3, LOW(q1.x)),        P56 = PK(HIW(q1.x), LOW(q1.y)); \
    const u64 P78 = PK(HIW(q1.y), LOW(q2.x)), P9A = PK(HIW(q2.x), LOW(q2.y)); \
    const u64 PBC = PK(HIW(q2.y), f12); \
    OST((PL)+0, (O)+0, P34, P56, P78, P9A); \
    OST((PL)+1, (O)+1, q1.x, q1.y, q2.x, q2.y); \
    OST((PL)+2, (O)+2, P56, P78, P9A, PBC); \
} while (0)

    char* o23base = outBase + (size_t)23 * (PLANE * 4);

    if (grp == 0) {
        EFROW(0, 0, 0);        // dy=-4: o0..4
        EMROW(528, 10, 5);     // dy=-1: o10..12
        {                      // o23 pixels 0,1
            const u64 n01 = LD1(srow + 1056);
            *(u64*)o23base = M2(M2(acc[32], inv01), n01);
        }
    } else if (grp == 1) {
        EFROW(352, 5, 0);      // dy=-2: o5..9
        EMROW(880, 20, 5);     // dy=+1: o20..22
    } else if (grp == 2) {
        {   // dy=0: o13..19
            const ulonglong2 q0 = LD2(srow + 704), q1 = LD2(srow + 720);
            const ulonglong2 q2 = LD2(srow + 736), q3 = LD2(srow + 752);
            const u64 P34 = PK(HIW(q0.y), LOW(q1.x)), P56 = PK(HIW(q1.x), LOW(q1.y));
            const u64 P78 = PK(HIW(q1.y), LOW(q2.x)), P9A = PK(HIW(q2.x), LOW(q2.y));
            const u64 PBC = PK(HIW(q2.y), LOW(q3.x));
            OST(13, 0, q0.x, q0.y, q1.x, q1.y);
            OST(14, 1, q0.y, q1.x, q1.y, q2.x);
            OST(15, 2, P34, P56, P78, P9A);
            OST(16, 3, q1.x, q1.y, q2.x, q2.y);
            OST(17, 4, P56, P78, P9A, PBC);
            OST(18, 5, q1.y, q2.x, q2.y, q3.x);
            OST(19, 6, q2.x, q2.y, q3.x, q3.y);
        }
        {   // o24 (dy+2, dx-2) + o23 pixels 2,3
            const u64 nd23 = LD1(srow + 1064);
            const ulonglong2 nm = LD2(srow + 1072);
            const u64 nd89 = LD1(srow + 1088);
            OST(24, 7, nd23, nm.x, nm.y, nd89);
            *(u64*)(o23base + 8) = M2(M2(acc[32], inv23), nd23);
        }
    } else {
        EFROW(1408, 28, 0);    // dy=+4: o28..32
        {   // dy=+2 dx{0,2,4}: o25..o27 + o23 pixels 4..7
            const ulonglong2 t1 = LD2(srow + 1072), t2 = LD2(srow + 1088), t3 = LD2(srow + 1104);
            OST(25, 5, t1.x, t1.y, t2.x, t2.y);
            OST(26, 6, t1.y, t2.x, t2.y, t3.x);
            OST(27, 7, t2.x, t2.y, t3.x, t3.y);
            *(u64*)(o23base + 16) = M2(M2(acc[32], inv45), t1.x);
            *(u64*)(o23base + 24) = M2(M2(acc[33], inv67), t1.y);
        }
    }
}

extern "C" void kernel_launch(void* const* d_in, const int* in_sizes, int n_in,
                              void* d_out, int out_size)
{
    const float* curr = (const float*)d_in[0];
    const float* prev = (const float*)d_in[1];
    float* out = (float*)d_out;

    cudaFuncSetAttribute(corr_kernel, cudaFuncAttributeMaxDynamicSharedMemorySize, SMEM_BYTES);

    dim3 grid(WW / TILE_W, HH / TILE_H, BB * 2);   // 6 x 8 x 16 = 768 half-CTAs
    corr_kernel<<<grid, NT, SMEM_BYTES>>>(curr, prev, out);
}

// round 17
// speedup vs baseline: 1.0987x; 1.0856x over previous
#include <cuda_runtime.h>
#include <cstdint>

#define HH 128
#define WW 192
#define CC_TOT 256
#define BB 8
#define TILE_W 32
#define TILE_H 16
#define HALO_H 24
#define CHUNK 8
#define NCHUNK (CC_TOT / CHUNK)          // 32
#define NT 256
#define PLANE ((size_t)HH * WW)

#define HROW 176
#define CROW 144
#define PSEC (HALO_H * HROW)              // 4224
#define CSEC (TILE_H * CROW)              // 2304
#define PREV_BUF (CHUNK * PSEC)           // 33792
#define CURR_BUF (CHUNK * CSEC)           // 18432
#define SM_PREV 0
#define SM_CURR (2 * PREV_BUF)            // 67584
#define SM_SSP  (SM_CURR + 2 * CURR_BUF)  // 104448
#define SM_CIV  (SM_SSP + PSEC)           // 108672
#define SMEM_BYTES (SM_CIV + CSEC)        // 110976 -> 2 CTAs/SM

typedef unsigned long long u64;

__device__ __forceinline__ void F2(u64 &d, u64 a, u64 b) {
    asm("fma.rn.f32x2 %0, %1, %2, %0;" : "+l"(d) : "l"(a), "l"(b));
}
__device__ __forceinline__ u64 M2(u64 a, u64 b) {
    u64 d; asm("mul.rn.f32x2 %0, %1, %2;" : "=l"(d) : "l"(a), "l"(b)); return d;
}
__device__ __forceinline__ u64 PK(unsigned a, unsigned b) {
    u64 d; asm("mov.b64 %0, {%1, %2};" : "=l"(d) : "r"(a), "r"(b)); return d;
}
__device__ __forceinline__ unsigned LOW(u64 a) {
    unsigned l, h; asm("mov.b64 {%0, %1}, %2;" : "=r"(l), "=r"(h) : "l"(a)); return l;
}
__device__ __forceinline__ unsigned HIW(u64 a) {
    unsigned l, h; asm("mov.b64 {%0, %1}, %2;" : "=r"(l), "=r"(h) : "l"(a)); return h;
}
__device__ __forceinline__ float FL(u64 a) { return __uint_as_float(LOW(a)); }
__device__ __forceinline__ float FH(u64 a) { return __uint_as_float(HIW(a)); }
__device__ __forceinline__ void cp16(uint32_t dst, const void* src, int szbytes) {
    asm volatile("cp.async.cg.shared.global [%0], [%1], 16, %2;\n"
                 :: "r"(dst), "l"(src), "r"(szbytes) : "memory");
}
__device__ __forceinline__ ulonglong2 LD2(const void* p) {
    return *reinterpret_cast<const ulonglong2*>(p);
}
__device__ __forceinline__ u64 LD1(const void* p) {
    return *reinterpret_cast<const u64*>(p);
}
__device__ __forceinline__ float GRD(float v) { return v > 0.f ? rsqrtf(v) : 0.f; }

__global__ void __launch_bounds__(NT, 2)
corr_kernel(const float* __restrict__ curr, const float* __restrict__ prev,
            float* __restrict__ out)
{
    extern __shared__ char smem[];

    const int tid = threadIdx.x;
    const int grp = tid >> 6;          // 4 groups of 64 threads
    const int gt  = tid & 63;
    const int xg  = gt & 3;            // 4 x-groups of 8 pixels
    const int ty  = gt >> 2;           // 16 rows
    const int x0  = blockIdx.x * TILE_W;
    const int y0  = blockIdx.y * TILE_H;
    const int bb  = blockIdx.z;

    const char* currB = (const char*)(curr + (size_t)bb * CC_TOT * PLANE);
    const char* prevB = (const char*)(prev + (size_t)bb * CC_TOT * PLANE);
    const uint32_t smA = (uint32_t)__cvta_generic_to_shared(smem);

    // ---- staging precompute ----
    const int psy = tid / 10, psx = tid - psy * 10;   // 240 prev f4 slots (24 rows x 10)
    const int pgy = y0 - 4 + psy, pgx = x0 - 4 + psx * 4;
    const bool doP = (tid < 240);
    const bool pok = doP && ((unsigned)pgy < HH) && ((unsigned)pgx < WW);
    const int pOff = pok ? (pgy * WW + pgx) * 4 : 0;
    const int psz  = pok ? 16 : 0;
    const uint32_t pRel = (uint32_t)(psy * HROW + psx * 16);
    const bool doC = (tid >= 128);
    const int cslot = tid - 128;
    const int csy = cslot >> 3, csx = cslot & 7;
    const int cOff = ((y0 + csy) * WW + x0 + csx * 4) * 4;
    const uint32_t cRel = (uint32_t)(csy * CROW + csx * 16);

    // ---- boundary prev-sq: 112 slots on G1(56)/G3(56) ----
    int fbj = -1;
    if (grp == 1)      { if (gt < 56) fbj = gt; }
    else if (grp == 3) { if (gt < 56) fbj = 56 + gt; }
    const bool doFB = (fbj >= 0);
    int fbRow = 0, fbCol = 0;
    if (fbj >= 0) {
        if (fbj < 40)      { fbRow = fbj / 10; fbCol = fbj - fbRow * 10; }
        else if (fbj < 80) { int i = fbj - 40; fbRow = 20 + i / 10; fbCol = i - (i / 10) * 10; }
        else               { int i = fbj - 80; fbRow = 4 + (i >> 1); fbCol = (i & 1) ? 9 : 0; }
    }
    const uint32_t fbOff = (uint32_t)(fbRow * HROW + fbCol * 16);

    // ---- accumulators (layout as R12/R13) ----
    u64 acc[34];
    #pragma unroll
    for (int i = 0; i < 34; i++) acc[i] = 0ull;
    u64 aux[4];
    #pragma unroll
    for (int i = 0; i < 4; i++) aux[i] = 0ull;

    auto issue = [&](const char* srcP, const char* srcC, uint32_t dP, uint32_t dC) {
        #pragma unroll
        for (int cc = 0; cc < CHUNK; cc++) {
            const size_t so = (size_t)cc * PLANE * 4;
            if (doP) cp16(dP + cc * PSEC + pRel, srcP + so + pOff, psz);
            if (doC) cp16(dC + cc * CSEC + cRel, srcC + so + cOff, 16);
        }
        asm volatile("cp.async.commit_group;\n" ::: "memory");
    };

    // prologue: stage chunk 0 -> buf 0
    issue(prevB, currB, smA + SM_PREV, smA + SM_CURR);

    const char* srcPs = prevB + (size_t)CHUNK * PLANE * 4;
    const char* srcCs = currB + (size_t)CHUNK * PLANE * 4;

    const int tyOff = ty * HROW + xg * 32;
    const int cvOff = ty * CROW + xg * 32;

#define FROW(O, RB) do { \
    const ulonglong2 q0 = LD2(RB), q1 = LD2((RB) + 16), q2 = LD2((RB) + 32), q3 = LD2((RB) + 48); \
    F2(acc[(O)*4+0],cv01,q0.x); F2(acc[(O)*4+1],cv23,q0.y); F2(acc[(O)*4+2],cv45,q1.x); F2(acc[(O)*4+3],cv67,q1.y); \
    F2(acc[(O)*4+4],cv01,q0.y); F2(acc[(O)*4+5],cv23,q1.x); F2(acc[(O)*4+6],cv45,q1.y); F2(acc[(O)*4+7],cv67,q2.x); \
    F2(acc[(O)*4+8],cv01,q1.x); F2(acc[(O)*4+9],cv23,q1.y); F2(acc[(O)*4+10],cv45,q2.x); F2(acc[(O)*4+11],cv67,q2.y); \
    F2(acc[(O)*4+12],cv01,q1.y); F2(acc[(O)*4+13],cv23,q2.x); F2(acc[(O)*4+14],cv45,q2.y); F2(acc[(O)*4+15],cv67,q3.x); \
    F2(acc[(O)*4+16],cv01,q2.x); F2(acc[(O)*4+17],cv23,q2.y); F2(acc[(O)*4+18],cv45,q3.x); F2(acc[(O)*4+19],cv67,q3.y); \
} while (0)

#define MROW(O, RB) do { \
    const unsigned f3 = *(const unsigned*)((RB) + 12); \
    const ulonglong2 q1 = LD2((RB) + 16), q2 = LD2((RB) + 32); \
    const unsigned f12 = *(const unsigned*)((RB) + 48); \
    const u64 P34 = PK(f3, LOW(q1.x)),      P56 = PK(HIW(q1.x), LOW(q1.y)); \
    const u64 P78 = PK(HIW(q1.y), LOW(q2.x)), P9A = PK(HIW(q2.x), LOW(q2.y)); \
    const u64 PBC = PK(HIW(q2.y), f12); \
    F2(acc[(O)*4+0],cv01,P34);  F2(acc[(O)*4+1],cv23,P56);  F2(acc[(O)*4+2],cv45,P78);  F2(acc[(O)*4+3],cv67,P9A); \
    F2(acc[(O)*4+4],cv01,q1.x); F2(acc[(O)*4+5],cv23,q1.y); F2(acc[(O)*4+6],cv45,q2.x); F2(acc[(O)*4+7],cv67,q2.y); \
    F2(acc[(O)*4+8],cv01,P56);  F2(acc[(O)*4+9],cv23,P78);  F2(acc[(O)*4+10],cv45,P9A); F2(acc[(O)*4+11],cv67,PBC); \
} while (0)

#define PREAMBLE \
    const char* secB = pbuf + cc * PSEC; \
    const char* rowB = secB + tyOff; \
    const char* cvP  = cbuf + cc * CSEC + cvOff; \
    const ulonglong2 CA = LD2(cvP), CB = LD2(cvP + 16); \
    const u64 cv01 = CA.x, cv23 = CA.y, cv45 = CB.x, cv67 = CB.y;

    #pragma unroll 1
    for (int k = 0; k < NCHUNK; k++) {
        asm volatile("cp.async.wait_group 0;\n" ::: "memory");
        __syncthreads();   // chunk k visible; all threads done with chunk k-1

        if (k < NCHUNK - 1) {
            issue(srcPs, srcCs,
                  smA + SM_PREV + ((k + 1) & 1) * PREV_BUF,
                  smA + SM_CURR + ((k + 1) & 1) * CURR_BUF);
            srcPs += (size_t)CHUNK * PLANE * 4;
            srcCs += (size_t)CHUNK * PLANE * 4;
        }

        const char* pbuf = smem + SM_PREV + (k & 1) * PREV_BUF;
        const char* cbuf = smem + SM_CURR + (k & 1) * CURR_BUF;

        if (grp == 0) {
            #pragma unroll 8
            for (int cc = 0; cc < CHUNK; cc++) {
                PREAMBLE
                F2(aux[0], cv01, cv01); F2(aux[1], cv23, cv23);   // ssq
                F2(aux[2], cv45, cv45); F2(aux[3], cv67, cv67);
                FROW(0, rowB);                      // dy=-4: o0..4
                MROW(5, rowB + 528);                // dy=-1: o10..12
                const u64 p01 = LD1(rowB + 1056);   // o23 pair01
                F2(acc[32], cv01, p01);
            }
        } else if (grp == 1) {
            #pragma unroll 8
            for (int cc = 0; cc < CHUNK; cc++) {
                PREAMBLE
                if (doFB) { const ulonglong2 v = LD2(secB + fbOff); F2(aux[0], v.x, v.x); F2(aux[1], v.y, v.y); }
                FROW(0, rowB + 352);                // dy=-2: o5..9
                MROW(5, rowB + 880);                // dy=+1: o20..22
            }
        } else if (grp == 2) {
            #pragma unroll 4
            for (int cc = 0; cc < CHUNK; cc++) {
                PREAMBLE
                {   // dy=0: o13..19 + interior prev-sq (aux)
                    const char* rb = rowB + 704;
                    const ulonglong2 q0 = LD2(rb), q1 = LD2(rb + 16), q2 = LD2(rb + 32), q3 = LD2(rb + 48);
                    F2(aux[0], q1.x, q1.x); F2(aux[1], q1.y, q1.y);
                    F2(aux[2], q2.x, q2.x); F2(aux[3], q2.y, q2.y);
                    const u64 P34 = PK(HIW(q0.y), LOW(q1.x)), P56 = PK(HIW(q1.x), LOW(q1.y));
                    const u64 P78 = PK(HIW(q1.y), LOW(q2.x)), P9A = PK(HIW(q2.x), LOW(q2.y));
                    const u64 PBC = PK(HIW(q2.y), LOW(q3.x));
                    F2(acc[0],cv01,q0.x);  F2(acc[1],cv23,q0.y);  F2(acc[2],cv45,q1.x);  F2(acc[3],cv67,q1.y);
                    F2(acc[4],cv01,q0.y);  F2(acc[5],cv23,q1.x);  F2(acc[6],cv45,q1.y);  F2(acc[7],cv67,q2.x);
                    F2(acc[8],cv01,P34);   F2(acc[9],cv23,P56);   F2(acc[10],cv45,P78);  F2(acc[11],cv67,P9A);
                    F2(acc[12],cv01,q1.x); F2(acc[13],cv23,q1.y); F2(acc[14],cv45,q2.x); F2(acc[15],cv67,q2.y);
                    F2(acc[16],cv01,P56);  F2(acc[17],cv23,P78);  F2(acc[18],cv45,P9A);  F2(acc[19],cv67,PBC);
                    F2(acc[20],cv01,q1.y); F2(acc[21],cv23,q2.x); F2(acc[22],cv45,q2.y); F2(acc[23],cv67,q3.x);
                    F2(acc[24],cv01,q2.x); F2(acc[25],cv23,q2.y); F2(acc[26],cv45,q3.x); F2(acc[27],cv67,q3.y);
                }
                {   // dy=+2: o24 (dx-2) + o23 pair23
                    const char* rb6 = rowB + 1056;
                    const u64 d23 = LD1(rb6 + 8);
                    const ulonglong2 m = LD2(rb6 + 16);
                    const u64 d89 = LD1(rb6 + 32);
                    F2(acc[28],cv01,d23); F2(acc[29],cv23,m.x); F2(acc[30],cv45,m.y); F2(acc[31],cv67,d89);
                    F2(acc[32], cv23, d23);
                }
            }
        } else {
            #pragma unroll 8
            for (int cc = 0; cc < CHUNK; cc++) {
                PREAMBLE
                if (doFB) { const ulonglong2 v = LD2(secB + fbOff); F2(aux[0], v.x, v.x); F2(aux[1], v.y, v.y); }
                FROW(0, rowB + 1408);               // dy=+4: o28..32
                {   // dy=+2 dx{0,2,4}: o25..o27 + o23 pairs45/67
                    const char* rb = rowB + 1056;
                    const ulonglong2 q1 = LD2(rb + 16), q2 = LD2(rb + 32), q3 = LD2(rb + 48);
                    F2(acc[20],cv01,q1.x); F2(acc[21],cv23,q1.y); F2(acc[22],cv45,q2.x); F2(acc[23],cv67,q2.y);
                    F2(acc[24],cv01,q1.y); F2(acc[25],cv23,q2.x); F2(acc[26],cv45,q2.y); F2(acc[27],cv67,q3.x);
                    F2(acc[28],cv01,q2.x); F2(acc[29],cv23,q2.y); F2(acc[30],cv45,q3.x); F2(acc[31],cv67,q3.y);
                    F2(acc[32], cv45, q1.x);
                    F2(acc[33], cv67, q1.y);
                }
            }
        }
    }

    // ---- epilogue: norms into smem ----
    {
        char* sspB = smem + SM_SSP;
        if (grp == 0) {
            float4 c0, c1;
            c0.x = rsqrtf(FL(aux[0])); c0.y = rsqrtf(FH(aux[0]));
            c0.z = rsqrtf(FL(aux[1])); c0.w = rsqrtf(FH(aux[1]));
            c1.x = rsqrtf(FL(aux[2])); c1.y = rsqrtf(FH(aux[2]));
            c1.z = rsqrtf(FL(aux[3])); c1.w = rsqrtf(FH(aux[3]));
            char* cdst = smem + SM_CIV + ty * CROW + xg * 32;
            *(float4*)cdst = c0;
            *(float4*)(cdst + 16) = c1;
        } else if (grp == 2) {
            float4 w0, w1;
            w0.x = GRD(FL(aux[0])); w0.y = GRD(FH(aux[0]));
            w0.z = GRD(FL(aux[1])); w0.w = GRD(FH(aux[1]));
            w1.x = GRD(FL(aux[2])); w1.y = GRD(FH(aux[2]));
            w1.z = GRD(FL(aux[3])); w1.w = GRD(FH(aux[3]));
            char* dst = sspB + (ty + 4) * HROW + xg * 32 + 16;
            *(float4*)dst = w0;
            *(float4*)(dst + 16) = w1;
        }
        if (doFB) {
            float4 w;
            w.x = GRD(FL(aux[0])); w.y = GRD(FH(aux[0]));
            w.z = GRD(FL(aux[1])); w.w = GRD(FH(aux[1]));
            *(float4*)(sspB + fbOff) = w;
        }
    }
    __syncthreads();

    u64 inv01, inv23, inv45, inv67;
    {
        const char* civ = smem + SM_CIV + ty * CROW + xg * 32;
        const ulonglong2 IA = LD2(civ), IB = LD2(civ + 16);
        inv01 = IA.x; inv23 = IA.y; inv45 = IB.x; inv67 = IB.y;
    }

    const char* srow = smem + SM_SSP + tyOff;
    char* outBase = (char*)(out + ((size_t)bb * 33 * HH + (y0 + ty)) * WW + x0 + xg * 8);

#define OST(PL, O, B0, B1, B2, B3) do { \
    ulonglong2 r0, r1; \
    r0.x = M2(M2(acc[(O)*4+0], inv01), (B0)); \
    r0.y = M2(M2(acc[(O)*4+1], inv23), (B1)); \
    r1.x = M2(M2(acc[(O)*4+2], inv45), (B2)); \
    r1.y = M2(M2(acc[(O)*4+3], inv67), (B3)); \
    char* _op = outBase + (size_t)(PL) * (PLANE * 4); \
    *(ulonglong2*)_op = r0; \
    *(ulonglong2*)(_op + 16) = r1; \
} while (0)

#define EFROW(SR, PL, O) do { \
    const ulonglong2 q0 = LD2(srow + (SR)), q1 = LD2(srow + (SR) + 16); \
    const ulonglong2 q2 = LD2(srow + (SR) + 32), q3 = LD2(srow + (SR) + 48); \
    OST((PL)+0, (O)+0, q0.x, q0.y, q1.x, q1.y); \
    OST((PL)+1, (O)+1, q0.y, q1.x, q1.y, q2.x); \
    OST((PL)+2, (O)+2, q1.x, q1.y, q2.x, q2.y); \
    OST((PL)+3, (O)+3, q1.y, q2.x, q2.y, q3.x); \
    OST((PL)+4, (O)+4, q2.x, q2.y, q3.x, q3.y); \
} while (0)

#define EMROW(SR, PL, O) do { \
    const unsigned f3 = *(const unsigned*)(srow + (SR) + 12); \
    const ulonglong2 q1 = LD2(srow + (SR) + 16), q2 = LD2(srow + (SR) + 32); \
    const unsigned f12 = *(const unsigned*)(srow + (SR) + 48); \
    const u64 P34 = PK(f3, LOW(q1.x)),        P56 = PK(HIW(q1.x), LOW(q1.y)); \
    const u64 P78 = PK(HIW(q1.y), LOW(q2.x)), P9A = PK(HIW(q2.x), LOW(q2.y)); \
    const u64 PBC = PK(HIW(q2.y), f12); \
    OST((PL)+0, (O)+0, P34, P56, P78, P9A); \
    OST((PL)+1, (O)+1, q1.x, q1.y, q2.x, q2.y); \
    OST((PL)+2, (O)+2, P56, P78, P9A, PBC); \
} while (0)

    char* o23base = outBase + (size_t)23 * (PLANE * 4);

    if (grp == 0) {
        EFROW(0, 0, 0);        // dy=-4: o0..4
        EMROW(528, 10, 5);     // dy=-1: o10..12
        {                      // o23 pixels 0,1
            const u64 n01 = LD1(srow + 1056);
            *(u64*)o23base = M2(M2(acc[32], inv01), n01);
        }
    } else if (grp == 1) {
        EFROW(352, 5, 0);      // dy=-2: o5..9
        EMROW(880, 20, 5);     // dy=+1: o20..22
    } else if (grp == 2) {
        {   // dy=0: o13..19
            const ulonglong2 q0 = LD2(srow + 704), q1 = LD2(srow + 720);
            const ulonglong2 q2 = LD2(srow + 736), q3 = LD2(srow + 752);
            const u64 P34 = PK(HIW(q0.y), LOW(q1.x)), P56 = PK(HIW(q1.x), LOW(q1.y));
            const u64 P78 = PK(HIW(q1.y), LOW(q2.x)), P9A = PK(HIW(q2.x), LOW(q2.y));
            const u64 PBC = PK(HIW(q2.y), LOW(q3.x));
            OST(13, 0, q0.x, q0.y, q1.x, q1.y);
            OST(14, 1, q0.y, q1.x, q1.y, q2.x);
            OST(15, 2, P34, P56, P78, P9A);
            OST(16, 3, q1.x, q1.y, q2.x, q2.y);
            OST(17, 4, P56, P78, P9A, PBC);
            OST(18, 5, q1.y, q2.x, q2.y, q3.x);
            OST(19, 6, q2.x, q2.y, q3.x, q3.y);
        }
        {   // o24 (dy+2, dx-2) + o23 pixels 2,3
            const u64 nd23 = LD1(srow + 1064);
            const ulonglong2 nm = LD2(srow + 1072);
            const u64 nd89 = LD1(srow + 1088);
            OST(24, 7, nd23, nm.x, nm.y, nd89);
            *(u64*)(o23base + 8) = M2(M2(acc[32], inv23), nd23);
        }
    } else {
        EFROW(1408, 28, 0);    // dy=+4: o28..32
        {   // dy=+2 dx{0,2,4}: o25..o27 + o23 pixels 4..7
            const ulonglong2 t1 = LD2(srow + 1072), t2 = LD2(srow + 1088), t3 = LD2(srow + 1104);
            OST(25, 5, t1.x, t1.y, t2.x, t2.y);
            OST(26, 6, t1.y, t2.x, t2.y, t3.x);
            OST(27, 7, t2.x, t2.y, t3.x, t3.y);
            *(u64*)(o23base + 16) = M2(M2(acc[32], inv45), t1.x);
            *(u64*)(o23base + 24) = M2(M2(acc[33], inv67), t1.y);
        }
    }
}

extern "C" void kernel_launch(void* const* d_in, const int* in_sizes, int n_in,
                              void* d_out, int out_size)
{
    const float* curr = (const float*)d_in[0];
    const float* prev = (const float*)d_in[1];
    float* out = (float*)d_out;

    cudaFuncSetAttribute(corr_kernel, cudaFuncAttributeMaxDynamicSharedMemorySize, SMEM_BYTES);

    dim3 grid(WW / TILE_W, HH / TILE_H, BB);   // 384 blocks
    corr_kernel<<<grid, NT, SMEM_BYTES>>>(curr, prev, out);
}